// round 2
// baseline (speedup 1.0000x reference)
#include <cuda_runtime.h>
#include <math.h>

#define T_STEPS 512
#define BATCH   64
#define IN_DIM  512
#define RNN_DIM 512

#define NCTA2   128   // persistent phase-2 grid

// 67MB scratch for pre-activations (x @ Wx + b), device-global (no allocs allowed)
__device__ float g_pre[(size_t)T_STEPS * BATCH * RNN_DIM];
__device__ unsigned int g_arrive;
__device__ unsigned int g_gen;

__global__ void init_kernel() {
    g_arrive = 0u;
    g_gen = 0u;
}

// ---------------------------------------------------------------------------
// Phase 1: pre[tb][j] = bias[j] + sum_d X[tb][d] * W[d][j]   (W rows 0..511)
// Classic 128x128x8 register-tiled fp32 GEMM, 256 threads, 8x8 per thread.
// ---------------------------------------------------------------------------
#define BM 128
#define BN 128
#define BK 8

__global__ __launch_bounds__(256) void gemm_pre_kernel(
    const float* __restrict__ X,
    const float* __restrict__ W,
    const float* __restrict__ bias)
{
    __shared__ float As[BK][BM];
    __shared__ float Bs[BK][BN];

    const int tid = threadIdx.x;
    const int bm = blockIdx.x;          // 256 blocks over M=32768
    const int bn = blockIdx.y;          // 4 blocks over N=512

    const float* Aptr = X + (size_t)bm * BM * IN_DIM;
    const float* Bptr = W + (size_t)bn * BN;

    const int tm = (tid / 16) * 8;
    const int tn = (tid % 16) * 8;

    // load assignments
    const int a_row = tid >> 1;            // 0..127
    const int a_kq  = (tid & 1) * 4;       // 0 or 4
    const int b_k   = tid >> 5;            // 0..7
    const int b_nq  = (tid & 31) * 4;      // 0..124

    float c[8][8];
    #pragma unroll
    for (int i = 0; i < 8; i++)
        #pragma unroll
        for (int j = 0; j < 8; j++)
            c[i][j] = 0.0f;

    for (int k0 = 0; k0 < IN_DIM; k0 += BK) {
        float4 av = *(const float4*)(Aptr + (size_t)a_row * IN_DIM + k0 + a_kq);
        float4 bv = *(const float4*)(Bptr + (size_t)(k0 + b_k) * RNN_DIM + b_nq);
        __syncthreads();
        As[a_kq + 0][a_row] = av.x;
        As[a_kq + 1][a_row] = av.y;
        As[a_kq + 2][a_row] = av.z;
        As[a_kq + 3][a_row] = av.w;
        *(float4*)&Bs[b_k][b_nq] = bv;
        __syncthreads();

        #pragma unroll
        for (int k = 0; k < BK; k++) {
            float ar[8], br[8];
            *(float4*)(ar)     = *(float4*)&As[k][tm];
            *(float4*)(ar + 4) = *(float4*)&As[k][tm + 4];
            *(float4*)(br)     = *(float4*)&Bs[k][tn];
            *(float4*)(br + 4) = *(float4*)&Bs[k][tn + 4];
            #pragma unroll
            for (int i = 0; i < 8; i++)
                #pragma unroll
                for (int j = 0; j < 8; j++)
                    c[i][j] += ar[i] * br[j];
        }
    }

    // epilogue: add bias, write to g_pre
    float4 bb0 = *(const float4*)(bias + bn * BN + tn);
    float4 bb1 = *(const float4*)(bias + bn * BN + tn + 4);
    #pragma unroll
    for (int i = 0; i < 8; i++) {
        size_t row = (size_t)bm * BM + tm + i;
        float4 v0, v1;
        v0.x = c[i][0] + bb0.x; v0.y = c[i][1] + bb0.y;
        v0.z = c[i][2] + bb0.z; v0.w = c[i][3] + bb0.w;
        v1.x = c[i][4] + bb1.x; v1.y = c[i][5] + bb1.y;
        v1.z = c[i][6] + bb1.z; v1.w = c[i][7] + bb1.w;
        *(float4*)(g_pre + row * RNN_DIM + bn * BN + tn)     = v0;
        *(float4*)(g_pre + row * RNN_DIM + bn * BN + tn + 4) = v1;
    }
}

// ---------------------------------------------------------------------------
// Phase 2: persistent sequential RNN.
// 128 CTAs = 32 j-blocks (16 cols) x 4 b-blocks (16 rows). 128 threads/CTA.
// Wh column slice resident in smem. h_t lives in d_out (out[t] == h_t).
// Custom generation grid barrier between steps.
// ---------------------------------------------------------------------------
__device__ __forceinline__ void grid_barrier(unsigned target) {
    __syncthreads();
    if (threadIdx.x == 0) {
        __threadfence();
        unsigned a = atomicAdd(&g_arrive, 1u);
        if (a == NCTA2 - 1) {
            atomicExch(&g_arrive, 0u);
            __threadfence();
            atomicExch(&g_gen, target);
        } else {
            while (*((volatile unsigned*)&g_gen) < target) { }
            __threadfence();
        }
    }
    __syncthreads();
}

#define JTILE 16
#define BTILE 16
#define RQ    128   // r-quarter size

__global__ __launch_bounds__(128) void rnn_seq_kernel(
    const float* __restrict__ W,
    const float* __restrict__ init_hidden,
    float* __restrict__ out)
{
    __shared__ float ws[RNN_DIM * JTILE];  // 32KB: Wh[r][jj], jj = local col
    __shared__ float hs[RQ * BTILE];       // 8KB: h[r_local][b], reused as reduction buf

    const int tid  = threadIdx.x;
    const int jblk = blockIdx.x & 31;   // 32 j-blocks
    const int bblk = blockIdx.x >> 5;   // 4 b-blocks
    const int j0 = jblk * JTILE;
    const int b0 = bblk * BTILE;

    // load Wh slice (rows 512..1023 of W, cols j0..j0+15) -- once
    for (int idx = tid; idx < RNN_DIM * (JTILE / 4); idx += 128) {
        int r  = idx >> 2;
        int jq = (idx & 3) * 4;
        float4 v = *(const float4*)(W + (size_t)(IN_DIM + r) * RNN_DIM + j0 + jq);
        *(float4*)&ws[r * JTILE + jq] = v;
    }

    // out[0] tile = broadcast init_hidden
    for (int o = tid; o < BTILE * JTILE; o += 128) {
        int b = o / JTILE, j = o % JTILE;
        out[(size_t)(b0 + b) * RNN_DIM + j0 + j] = init_hidden[j0 + j];
    }
    __threadfence();
    grid_barrier(1u);

    const int kg = tid >> 4;            // 0..7 : k-split groups
    const int tt = tid & 15;
    const int bq = (tt >> 2) * 4;       // 0,4,8,12
    const int jq = (tt & 3) * 4;        // 0,4,8,12

    const int ld_b  = tid & 15;         // smem h-transpose load assignment
    const int ld_rg = tid >> 4;         // 8 groups x 16 r per quarter

    unsigned target = 2u;
    for (int t = 0; t < T_STEPS - 1; t++, target++) {
        const float* hsrc = out + ((size_t)t * BATCH + b0) * RNN_DIM;
        float c[4][4];
        #pragma unroll
        for (int i = 0; i < 4; i++)
            #pragma unroll
            for (int j = 0; j < 4; j++)
                c[i][j] = 0.0f;

        #pragma unroll 1
        for (int q = 0; q < 4; q++) {
            __syncthreads();   // hs free
            // load h[b0..b0+15][q*128 .. q*128+127], transposed to hs[r][b]
            {
                const float* src = hsrc + (size_t)ld_b * RNN_DIM + q * RQ + ld_rg * 16;
                #pragma unroll
                for (int rr = 0; rr < 16; rr += 4) {
                    float4 v = *(const float4*)(src + rr);
                    int r = ld_rg * 16 + rr;
                    hs[(r + 0) * BTILE + ld_b] = v.x;
                    hs[(r + 1) * BTILE + ld_b] = v.y;
                    hs[(r + 2) * BTILE + ld_b] = v.z;
                    hs[(r + 3) * BTILE + ld_b] = v.w;
                }
            }
            __syncthreads();
            const float* wq = ws + (size_t)q * RQ * JTILE;
            #pragma unroll
            for (int rr = 0; rr < 16; rr++) {
                int rl = kg * 16 + rr;
                float4 hv = *(float4*)&hs[rl * BTILE + bq];
                float4 wv = *(const float4*)&wq[rl * JTILE + jq];
                c[0][0] += hv.x * wv.x; c[0][1] += hv.x * wv.y;
                c[0][2] += hv.x * wv.z; c[0][3] += hv.x * wv.w;
                c[1][0] += hv.y * wv.x; c[1][1] += hv.y * wv.y;
                c[1][2] += hv.y * wv.z; c[1][3] += hv.y * wv.w;
                c[2][0] += hv.z * wv.x; c[2][1] += hv.z * wv.y;
                c[2][2] += hv.z * wv.z; c[2][3] += hv.z * wv.w;
                c[3][0] += hv.w * wv.x; c[3][1] += hv.w * wv.y;
                c[3][2] += hv.w * wv.z; c[3][3] += hv.w * wv.w;
            }
        }

        // k-split reduction through hs (8 x 16 x 16 floats = 8KB, fits exactly)
        __syncthreads();
        float* red = hs;
        #pragma unroll
        for (int i = 0; i < 4; i++)
            #pragma unroll
            for (int j = 0; j < 4; j++)
                red[(kg * BTILE + bq + i) * JTILE + jq + j] = c[i][j];
        __syncthreads();

        const float* prep = g_pre + ((size_t)t * BATCH + b0) * RNN_DIM + j0;
        float* outp = out + ((size_t)(t + 1) * BATCH + b0) * RNN_DIM + j0;
        for (int o = tid; o < BTILE * JTILE; o += 128) {
            int b = o / JTILE, j = o % JTILE;
            float s = 0.0f;
            #pragma unroll
            for (int g = 0; g < 8; g++)
                s += red[(g * BTILE + b) * JTILE + j];
            float v = tanhf(s + prep[(size_t)b * RNN_DIM + j]);
            outp[(size_t)b * RNN_DIM + j] = v;
        }
        __threadfence();
        grid_barrier(target);
    }
}

// ---------------------------------------------------------------------------
extern "C" void kernel_launch(void* const* d_in, const int* in_sizes, int n_in,
                              void* d_out, int out_size)
{
    const float* X    = (const float*)d_in[0];  // [T, B, IN_DIM]
    const float* W    = (const float*)d_in[1];  // [IN_DIM + RNN_DIM, RNN_DIM]
    const float* bias = (const float*)d_in[2];  // [RNN_DIM]
    const float* h0   = (const float*)d_in[3];  // [RNN_DIM]
    float* out = (float*)d_out;                 // [T, B, RNN_DIM]

    init_kernel<<<1, 1>>>();

    dim3 g1((T_STEPS * BATCH) / BM, RNN_DIM / BN);  // (256, 4)
    gemm_pre_kernel<<<g1, 256>>>(X, W, bias);

    rnn_seq_kernel<<<NCTA2, 128>>>(W, h0, out);
}

// round 3
// speedup vs baseline: 1.4178x; 1.4178x over previous
#include <cuda_runtime.h>
#include <math.h>

#define T_STEPS 512
#define BATCH   64
#define IN_DIM  512
#define RNN_DIM 512

#define NCTA2   128   // persistent phase-2 grid (1 CTA/SM, <=148)
#define NTHR2   256   // 8 warps

// scratch (no allocs allowed): pre-activations + transposed-h ping-pong + barrier state
__device__ float g_pre[(size_t)T_STEPS * BATCH * RNN_DIM];      // 64MB
__device__ float g_hT[2][RNN_DIM * BATCH];                       // [parity][r][b], 256KB
__device__ unsigned long long g_arrive;
__device__ unsigned long long g_gen;

// ---------------------------------------------------------------------------
// Phase 1: pre[tb][j] = bias[j] + sum_d X[tb][d] * W[d][j]   (W rows 0..511)
// 128x128x8 register-tiled fp32 GEMM, 256 threads, 8x8 per thread.
// Block (0,0) also resets the phase-2 grid-barrier state (stream-ordered:
// the previous rnn kernel has fully completed, so this is race-free).
// ---------------------------------------------------------------------------
#define BM 128
#define BN 128
#define BK 8

__global__ __launch_bounds__(256) void gemm_pre_kernel(
    const float* __restrict__ X,
    const float* __restrict__ W,
    const float* __restrict__ bias)
{
    if (blockIdx.x == 0 && blockIdx.y == 0 && threadIdx.x == 0) {
        g_arrive = 0ULL;
        g_gen    = 0ULL;
    }

    __shared__ float As[BK][BM];
    __shared__ float Bs[BK][BN];

    const int tid = threadIdx.x;
    const int bm = blockIdx.x;          // 256 blocks over M=32768
    const int bn = blockIdx.y;          // 4 blocks over N=512

    const float* Aptr = X + (size_t)bm * BM * IN_DIM;
    const float* Bptr = W + (size_t)bn * BN;

    const int tm = (tid / 16) * 8;
    const int tn = (tid % 16) * 8;

    const int a_row = tid >> 1;
    const int a_kq  = (tid & 1) * 4;
    const int b_k   = tid >> 5;
    const int b_nq  = (tid & 31) * 4;

    float c[8][8];
    #pragma unroll
    for (int i = 0; i < 8; i++)
        #pragma unroll
        for (int j = 0; j < 8; j++)
            c[i][j] = 0.0f;

    for (int k0 = 0; k0 < IN_DIM; k0 += BK) {
        float4 av = *(const float4*)(Aptr + (size_t)a_row * IN_DIM + k0 + a_kq);
        float4 bv = *(const float4*)(Bptr + (size_t)(k0 + b_k) * RNN_DIM + b_nq);
        __syncthreads();
        As[a_kq + 0][a_row] = av.x;
        As[a_kq + 1][a_row] = av.y;
        As[a_kq + 2][a_row] = av.z;
        As[a_kq + 3][a_row] = av.w;
        *(float4*)&Bs[b_k][b_nq] = bv;
        __syncthreads();

        #pragma unroll
        for (int k = 0; k < BK; k++) {
            float ar[8], br[8];
            *(float4*)(ar)     = *(float4*)&As[k][tm];
            *(float4*)(ar + 4) = *(float4*)&As[k][tm + 4];
            *(float4*)(br)     = *(float4*)&Bs[k][tn];
            *(float4*)(br + 4) = *(float4*)&Bs[k][tn + 4];
            #pragma unroll
            for (int i = 0; i < 8; i++)
                #pragma unroll
                for (int j = 0; j < 8; j++)
                    c[i][j] += ar[i] * br[j];
        }
    }

    float4 bb0 = *(const float4*)(bias + bn * BN + tn);
    float4 bb1 = *(const float4*)(bias + bn * BN + tn + 4);
    #pragma unroll
    for (int i = 0; i < 8; i++) {
        size_t row = (size_t)bm * BM + tm + i;
        float4 v0, v1;
        v0.x = c[i][0] + bb0.x; v0.y = c[i][1] + bb0.y;
        v0.z = c[i][2] + bb0.z; v0.w = c[i][3] + bb0.w;
        v1.x = c[i][4] + bb1.x; v1.y = c[i][5] + bb1.y;
        v1.z = c[i][6] + bb1.z; v1.w = c[i][7] + bb1.w;
        *(float4*)(g_pre + row * RNN_DIM + bn * BN + tn)     = v0;
        *(float4*)(g_pre + row * RNN_DIM + bn * BN + tn + 4) = v1;
    }
}

// ---------------------------------------------------------------------------
// Phase 2: persistent sequential RNN.
// 128 CTAs = 32 j-blocks x 4 b-blocks, each computes h_next[16b x 16j].
// 256 threads: 16 k-groups (strided k = kg + 16*kk) x 16 tile positions (4x4).
// Wh column slice resident in smem; h kept transposed in gmem ping-pong g_hT.
// Grid barrier: RED arrivals + single poller release.
// ---------------------------------------------------------------------------
__device__ __forceinline__ void grid_barrier(unsigned long long step)
{
    __syncthreads();
    if (threadIdx.x == 0) {
        atomicAdd(&g_arrive, 1ULL);            // result unused -> REDG
        if (blockIdx.x == 0) {
            while (*(volatile unsigned long long*)&g_arrive <
                   (unsigned long long)NCTA2 * step) { }
            *(volatile unsigned long long*)&g_gen = step;
        } else {
            while (*(volatile unsigned long long*)&g_gen < step) { }
        }
        __threadfence();
    }
    __syncthreads();
}

extern __shared__ float smem2[];

__global__ __launch_bounds__(NTHR2) void rnn_seq_kernel(
    const float* __restrict__ W,
    const float* __restrict__ init_hidden,
    float* __restrict__ out)
{
    float* ws = smem2;                 // [512][16] Wh slice, 32KB
    float* hs = smem2 + RNN_DIM * 16;  // [512][16] h slab, 32KB (reused as red[16][256])

    const int tid  = threadIdx.x;
    const int jblk = blockIdx.x & 31;
    const int bblk = blockIdx.x >> 5;
    const int j0 = jblk * 16;
    const int b0 = bblk * 16;

    // load Wh slice (rows 512..1023 of W, cols j0..j0+15) once
    #pragma unroll
    for (int i = 0; i < 8; i++) {
        int idx = tid + i * NTHR2;         // 0..2047 quads
        int r = idx >> 2, q = (idx & 3) * 4;
        *(float4*)&ws[r * 16 + q] =
            *(const float4*)(W + (size_t)(IN_DIM + r) * RNN_DIM + j0 + q);
    }

    // out[0] tile = broadcast init_hidden
    {
        int b = tid >> 4, j = tid & 15;
        out[(size_t)(b0 + b) * RNN_DIM + j0 + j] = init_hidden[j0 + j];
    }
    // g_hT[0][r][b] = init_hidden[r]  (only jblk==0 CTAs write, one slab each)
    if (jblk == 0) {
        int kbase = (tid >> 2) * 8;
        int q = (tid & 3) * 4;
        #pragma unroll
        for (int kk = 0; kk < 8; kk++) {
            int k = kbase + kk;
            float v = init_hidden[k];
            float4 vv = make_float4(v, v, v, v);
            *(float4*)&g_hT[0][k * BATCH + b0 + q] = vv;
        }
    }
    __threadfence();
    grid_barrier(1ULL);

    const int kg = tid >> 4;              // 0..15 k-group
    const int tt = tid & 15;
    const int bq = (tt >> 2) * 4;         // 0,4,8,12
    const int jq = (tt & 3) * 4;          // 0,4,8,12
    const int fb = tid >> 4;              // final-pass b
    const int fj = tid & 15;              // final-pass j

    for (int t = 0; t < T_STEPS - 1; t++) {
        // stage h slab [512][b0..b0+15] (already transposed in g_hT)
        const float* hsrc = g_hT[t & 1];
        #pragma unroll
        for (int i = 0; i < 8; i++) {
            int idx = tid + i * NTHR2;
            int r = idx >> 2, q = (idx & 3) * 4;
            *(float4*)&hs[r * 16 + q] = *(const float4*)(hsrc + r * BATCH + b0 + q);
        }
        __syncthreads();

        float c[4][4];
        #pragma unroll
        for (int i = 0; i < 4; i++)
            #pragma unroll
            for (int j = 0; j < 4; j++)
                c[i][j] = 0.0f;

        #pragma unroll 4
        for (int kk = 0; kk < 32; kk++) {
            int k = kg + (kk << 4);
            float4 hv = *(float4*)&hs[k * 16 + bq];
            float4 wv = *(float4*)&ws[k * 16 + jq];
            c[0][0] += hv.x * wv.x; c[0][1] += hv.x * wv.y;
            c[0][2] += hv.x * wv.z; c[0][3] += hv.x * wv.w;
            c[1][0] += hv.y * wv.x; c[1][1] += hv.y * wv.y;
            c[1][2] += hv.y * wv.z; c[1][3] += hv.y * wv.w;
            c[2][0] += hv.z * wv.x; c[2][1] += hv.z * wv.y;
            c[2][2] += hv.z * wv.z; c[2][3] += hv.z * wv.w;
            c[3][0] += hv.w * wv.x; c[3][1] += hv.w * wv.y;
            c[3][2] += hv.w * wv.z; c[3][3] += hv.w * wv.w;
        }
        __syncthreads();   // all warps done reading hs

        // k-split partials: red[kg][b][j] overlaid on hs (16KB of 32KB)
        float* red = hs;
        #pragma unroll
        for (int i = 0; i < 4; i++)
            #pragma unroll
            for (int j = 0; j < 4; j++)
                red[kg * 256 + (bq + i) * 16 + (jq + j)] = c[i][j];
        __syncthreads();

        // final: one output per thread
        float s = 0.0f;
        #pragma unroll
        for (int g = 0; g < 16; g++)
            s += red[g * 256 + tid];     // tid == b*16 + j, conflict-free
        s += g_pre[((size_t)t * BATCH + b0 + fb) * RNN_DIM + j0 + fj];
        float h = tanhf(s);
        out[((size_t)(t + 1) * BATCH + b0 + fb) * RNN_DIM + j0 + fj] = h;
        g_hT[(t + 1) & 1][(j0 + fj) * BATCH + b0 + fb] = h;

        if (t < T_STEPS - 2) {           // last step needs no barrier
            __threadfence();
            grid_barrier((unsigned long long)(t + 2));
        }
    }
}

// ---------------------------------------------------------------------------
extern "C" void kernel_launch(void* const* d_in, const int* in_sizes, int n_in,
                              void* d_out, int out_size)
{
    const float* X    = (const float*)d_in[0];  // [T, B, IN_DIM]
    const float* W    = (const float*)d_in[1];  // [IN_DIM + RNN_DIM, RNN_DIM]
    const float* bias = (const float*)d_in[2];  // [RNN_DIM]
    const float* h0   = (const float*)d_in[3];  // [RNN_DIM]
    float* out = (float*)d_out;                 // [T, B, RNN_DIM]

    static int smem_set = 0;
    (void)smem_set;
    cudaFuncSetAttribute(rnn_seq_kernel,
                         cudaFuncAttributeMaxDynamicSharedMemorySize, 65536);

    dim3 g1((T_STEPS * BATCH) / BM, RNN_DIM / BN);  // (256, 4)
    gemm_pre_kernel<<<g1, 256>>>(X, W, bias);

    rnn_seq_kernel<<<NCTA2, NTHR2, 65536>>>(W, h0, out);
}

// round 4
// speedup vs baseline: 1.7737x; 1.2510x over previous
#include <cuda_runtime.h>
#include <math.h>

#define T_STEPS 512
#define BATCH   64
#define IN_DIM  512
#define RNN_DIM 512

#define NCTA2   128   // persistent phase-2 grid (32 jblk x 4 bblk)
#define NTHR2   256
#define GRP_SZ  32    // CTAs per bblk group

// scratch (no allocs allowed)
__device__ float g_pre[(size_t)T_STEPS * BATCH * RNN_DIM];   // 64MB
__device__ float g_hT[2][RNN_DIM * BATCH];                    // [parity][r][b]
__device__ unsigned long long g_grp[4 * 16];                  // group ctrs, 128B apart

// ---------------------------------------------------------------------------
// Phase 1: pre[tb][j] = bias[j] + sum_d X[tb][d] * W[d][j]   (W rows 0..511)
// 128x128x8 register-tiled fp32 GEMM. Block (0,0) resets barrier state
// (stream-ordered vs the previous rnn kernel -> race-free).
// ---------------------------------------------------------------------------
#define BM 128
#define BN 128
#define BK 8

__global__ __launch_bounds__(256) void gemm_pre_kernel(
    const float* __restrict__ X,
    const float* __restrict__ W,
    const float* __restrict__ bias)
{
    if (blockIdx.x == 0 && blockIdx.y == 0 && threadIdx.x < 4)
        g_grp[threadIdx.x * 16] = 0ULL;

    __shared__ float As[BK][BM];
    __shared__ float Bs[BK][BN];

    const int tid = threadIdx.x;
    const int bm = blockIdx.x;
    const int bn = blockIdx.y;

    const float* Aptr = X + (size_t)bm * BM * IN_DIM;
    const float* Bptr = W + (size_t)bn * BN;

    const int tm = (tid / 16) * 8;
    const int tn = (tid % 16) * 8;

    const int a_row = tid >> 1;
    const int a_kq  = (tid & 1) * 4;
    const int b_k   = tid >> 5;
    const int b_nq  = (tid & 31) * 4;

    float c[8][8];
    #pragma unroll
    for (int i = 0; i < 8; i++)
        #pragma unroll
        for (int j = 0; j < 8; j++)
            c[i][j] = 0.0f;

    for (int k0 = 0; k0 < IN_DIM; k0 += BK) {
        float4 av = *(const float4*)(Aptr + (size_t)a_row * IN_DIM + k0 + a_kq);
        float4 bv = *(const float4*)(Bptr + (size_t)(k0 + b_k) * RNN_DIM + b_nq);
        __syncthreads();
        As[a_kq + 0][a_row] = av.x;
        As[a_kq + 1][a_row] = av.y;
        As[a_kq + 2][a_row] = av.z;
        As[a_kq + 3][a_row] = av.w;
        *(float4*)&Bs[b_k][b_nq] = bv;
        __syncthreads();

        #pragma unroll
        for (int k = 0; k < BK; k++) {
            float ar[8], br[8];
            *(float4*)(ar)     = *(float4*)&As[k][tm];
            *(float4*)(ar + 4) = *(float4*)&As[k][tm + 4];
            *(float4*)(br)     = *(float4*)&Bs[k][tn];
            *(float4*)(br + 4) = *(float4*)&Bs[k][tn + 4];
            #pragma unroll
            for (int i = 0; i < 8; i++)
                #pragma unroll
                for (int j = 0; j < 8; j++)
                    c[i][j] += ar[i] * br[j];
        }
    }

    float4 bb0 = *(const float4*)(bias + bn * BN + tn);
    float4 bb1 = *(const float4*)(bias + bn * BN + tn + 4);
    #pragma unroll
    for (int i = 0; i < 8; i++) {
        size_t row = (size_t)bm * BM + tm + i;
        float4 v0, v1;
        v0.x = c[i][0] + bb0.x; v0.y = c[i][1] + bb0.y;
        v0.z = c[i][2] + bb0.z; v0.w = c[i][3] + bb0.w;
        v1.x = c[i][4] + bb1.x; v1.y = c[i][5] + bb1.y;
        v1.z = c[i][6] + bb1.z; v1.w = c[i][7] + bb1.w;
        *(float4*)(g_pre + row * RNN_DIM + bn * BN + tn)     = v0;
        *(float4*)(g_pre + row * RNN_DIM + bn * BN + tn + 4) = v1;
    }
}

// ---------------------------------------------------------------------------
// Phase 2: persistent sequential RNN, 4 independent bblk chains.
// ---------------------------------------------------------------------------
__device__ __forceinline__ void group_barrier(int grp, unsigned long long step)
{
    __syncthreads();
    if (threadIdx.x == 0) {
        __threadfence();
        atomicAdd(&g_grp[grp * 16], 1ULL);     // no-return use -> REDG path
        volatile unsigned long long* ctr =
            (volatile unsigned long long*)&g_grp[grp * 16];
        unsigned long long need = (unsigned long long)GRP_SZ * step;
        while (*ctr < need) { }
        __threadfence();
    }
    __syncthreads();
}

extern __shared__ float smem2[];

__global__ __launch_bounds__(NTHR2) void rnn_seq_kernel(
    const float* __restrict__ W,
    const float* __restrict__ init_hidden,
    float* __restrict__ out)
{
    float* ws = smem2;                 // [512][16] Wh slice, 32KB
    float* hs = smem2 + RNN_DIM * 16;  // [512][16] h slab, 32KB (rows<256 reused as red)

    const int tid  = threadIdx.x;
    const int jblk = blockIdx.x & 31;
    const int bblk = blockIdx.x >> 5;
    const int j0 = jblk * 16;
    const int b0 = bblk * 16;

    // Wh slice (rows 512..1023 of W, cols j0..j0+15), loaded once
    #pragma unroll
    for (int i = 0; i < 8; i++) {
        int idx = tid + i * NTHR2;
        int r = idx >> 2, q = (idx & 3) * 4;
        *(float4*)&ws[r * 16 + q] =
            *(const float4*)(W + (size_t)(IN_DIM + r) * RNN_DIM + j0 + q);
    }

    // out[0] tile = broadcast init_hidden
    {
        int b = tid >> 4, j = tid & 15;
        out[(size_t)(b0 + b) * RNN_DIM + j0 + j] = init_hidden[j0 + j];
    }
    // g_hT[0][r][b0..b0+15] = init_hidden[r]  (one CTA per group: jblk==0)
    if (jblk == 0) {
        int kbase = (tid >> 2) * 8;
        int q = (tid & 3) * 4;
        #pragma unroll
        for (int kk = 0; kk < 8; kk++) {
            int k = kbase + kk;
            float v = init_hidden[k];
            *(float4*)&g_hT[0][k * BATCH + b0 + q] = make_float4(v, v, v, v);
        }
    }
    group_barrier(bblk, 1ULL);

    const int kg = tid >> 4;              // 0..15 k-group
    const int tt = tid & 15;
    const int bq = (tt >> 2) * 4;         // 0,4,8,12
    const int jq = (tt & 3) * 4;          // 0,4,8,12
    const int fb = tid >> 4;              // epilogue b
    const int fj = tid & 15;              // epilogue j

    for (int t = 0; t < T_STEPS - 1; t++) {
        const float* hsrc = g_hT[t & 1];

        // --- stage half0 (rows 0..255) ---
        float4 r0[4];
        #pragma unroll
        for (int i = 0; i < 4; i++) {
            int idx = tid + i * NTHR2;          // rows 0..255
            int r = idx >> 2, q = (idx & 3) * 4;
            r0[i] = *(const float4*)(hsrc + r * BATCH + b0 + q);
        }
        // prefetch pre-activation (independent; consumed at epilogue)
        float pre = g_pre[((size_t)t * BATCH + b0 + fb) * RNN_DIM + j0 + fj];
        #pragma unroll
        for (int i = 0; i < 4; i++) {
            int idx = tid + i * NTHR2;
            int r = idx >> 2, q = (idx & 3) * 4;
            *(float4*)&hs[r * 16 + q] = r0[i];
        }
        __syncthreads();

        // --- issue half1 loads (rows 256..511), overlap with compute half0 ---
        float4 r1[4];
        #pragma unroll
        for (int i = 0; i < 4; i++) {
            int idx = tid + (i + 4) * NTHR2;    // rows 256..511
            int r = idx >> 2, q = (idx & 3) * 4;
            r1[i] = *(const float4*)(hsrc + r * BATCH + b0 + q);
        }

        float c[4][4];
        #pragma unroll
        for (int i = 0; i < 4; i++)
            #pragma unroll
            for (int j = 0; j < 4; j++)
                c[i][j] = 0.0f;

        #pragma unroll 4
        for (int kk = 0; kk < 16; kk++) {       // k in [0,256)
            int k = kg + (kk << 4);
            float4 hv = *(float4*)&hs[k * 16 + bq];
            float4 wv = *(float4*)&ws[k * 16 + jq];
            c[0][0] += hv.x * wv.x; c[0][1] += hv.x * wv.y;
            c[0][2] += hv.x * wv.z; c[0][3] += hv.x * wv.w;
            c[1][0] += hv.y * wv.x; c[1][1] += hv.y * wv.y;
            c[1][2] += hv.y * wv.z; c[1][3] += hv.y * wv.w;
            c[2][0] += hv.z * wv.x; c[2][1] += hv.z * wv.y;
            c[2][2] += hv.z * wv.z; c[2][3] += hv.z * wv.w;
            c[3][0] += hv.w * wv.x; c[3][1] += hv.w * wv.y;
            c[3][2] += hv.w * wv.z; c[3][3] += hv.w * wv.w;
        }

        #pragma unroll
        for (int i = 0; i < 4; i++) {
            int idx = tid + (i + 4) * NTHR2;
            int r = idx >> 2, q = (idx & 3) * 4;
            *(float4*)&hs[r * 16 + q] = r1[i];
        }
        __syncthreads();

        #pragma unroll 4
        for (int kk = 16; kk < 32; kk++) {      // k in [256,512)
            int k = kg + (kk << 4);
            float4 hv = *(float4*)&hs[k * 16 + bq];
            float4 wv = *(float4*)&ws[k * 16 + jq];
            c[0][0] += hv.x * wv.x; c[0][1] += hv.x * wv.y;
            c[0][2] += hv.x * wv.z; c[0][3] += hv.x * wv.w;
            c[1][0] += hv.y * wv.x; c[1][1] += hv.y * wv.y;
            c[1][2] += hv.y * wv.z; c[1][3] += hv.y * wv.w;
            c[2][0] += hv.z * wv.x; c[2][1] += hv.z * wv.y;
            c[2][2] += hv.z * wv.z; c[2][3] += hv.z * wv.w;
            c[3][0] += hv.w * wv.x; c[3][1] += hv.w * wv.y;
            c[3][2] += hv.w * wv.z; c[3][3] += hv.w * wv.w;
        }

        // k-split partials: red[kg][b][j] overlays hs rows < 256 (16KB).
        // Safe without a pre-sync: after sync#2 no thread reads rows < 256,
        // and compute half1 touches only rows >= 256.
        float* red = hs;
        #pragma unroll
        for (int i = 0; i < 4; i++)
            #pragma unroll
            for (int j = 0; j < 4; j++)
                red[kg * 256 + (bq + i) * 16 + (jq + j)] = c[i][j];
        __syncthreads();

        float s = 0.0f;
        #pragma unroll
        for (int g = 0; g < 16; g++)
            s += red[g * 256 + tid];            // tid == b*16+j, conflict-free
        float h = tanhf(s + pre);
        out[((size_t)(t + 1) * BATCH + b0 + fb) * RNN_DIM + j0 + fj] = h;
        g_hT[(t + 1) & 1][(j0 + fj) * BATCH + b0 + fb] = h;

        if (t < T_STEPS - 2)
            group_barrier(bblk, (unsigned long long)(t + 2));
    }
}

// ---------------------------------------------------------------------------
extern "C" void kernel_launch(void* const* d_in, const int* in_sizes, int n_in,
                              void* d_out, int out_size)
{
    const float* X    = (const float*)d_in[0];  // [T, B, IN_DIM]
    const float* W    = (const float*)d_in[1];  // [IN_DIM + RNN_DIM, RNN_DIM]
    const float* bias = (const float*)d_in[2];  // [RNN_DIM]
    const float* h0   = (const float*)d_in[3];  // [RNN_DIM]
    float* out = (float*)d_out;                 // [T, B, RNN_DIM]

    cudaFuncSetAttribute(rnn_seq_kernel,
                         cudaFuncAttributeMaxDynamicSharedMemorySize, 65536);

    dim3 g1((T_STEPS * BATCH) / BM, RNN_DIM / BN);  // (256, 4)
    gemm_pre_kernel<<<g1, 256>>>(X, W, bias);

    rnn_seq_kernel<<<NCTA2, NTHR2, 65536>>>(W, h0, out);
}